// round 1
// baseline (speedup 1.0000x reference)
#include <cuda_runtime.h>
#include <math.h>

// Problem constants
#define BATCH   2
#define SEQ     2048
#define CDIM    1024
#define NHEAD   16
#define HDIM    64
#define C3      3072
#define MROWS   4096            // BATCH*SEQ

// Scratch (device globals — no runtime allocation allowed)
__device__ float g_qkv[MROWS * C3];    // [4096, 3072]
__device__ float g_att[MROWS * CDIM];  // [4096, 1024]

// ---------------------------------------------------------------------------
// Classic 128x128x8 SGEMM with bias: out[M,N] = A[M,K] @ W[K,N] + bias[N]
// 256 threads, 8x8 accumulators per thread. All dims divide evenly here.
// ---------------------------------------------------------------------------
__global__ void __launch_bounds__(256)
sgemm_bias_kernel(const float* __restrict__ A, const float* __restrict__ W,
                  const float* __restrict__ bias, float* __restrict__ out,
                  int M, int N, int K)
{
    __shared__ float As[8][128];
    __shared__ float Bs[8][128];

    const int tid = threadIdx.x;
    const int blockRow = blockIdx.y;
    const int blockCol = blockIdx.x;

    // A tile loader: 128 rows x 8 cols -> one float4 per thread
    const int aRow = tid >> 1;           // 0..127
    const int aCol = (tid & 1) * 4;      // 0 or 4
    // W tile loader: 8 rows x 128 cols -> one float4 per thread
    const int bRow = tid >> 5;           // 0..7
    const int bCol = (tid & 31) * 4;     // 0..124

    const float* Aptr = A + (size_t)(blockRow * 128 + aRow) * K + aCol;
    const float* Wptr = W + (size_t)bRow * N + blockCol * 128 + bCol;

    const int ty = tid >> 4;             // 0..15
    const int tx = tid & 15;             // 0..15

    float acc[8][8];
#pragma unroll
    for (int i = 0; i < 8; ++i)
#pragma unroll
        for (int j = 0; j < 8; ++j) acc[i][j] = 0.f;

    for (int kt = 0; kt < K; kt += 8) {
        float4 a4 = *(const float4*)Aptr;  Aptr += 8;
        float4 b4 = *(const float4*)Wptr;  Wptr += (size_t)8 * N;

        As[aCol + 0][aRow] = a4.x;
        As[aCol + 1][aRow] = a4.y;
        As[aCol + 2][aRow] = a4.z;
        As[aCol + 3][aRow] = a4.w;
        *(float4*)&Bs[bRow][bCol] = b4;
        __syncthreads();

#pragma unroll
        for (int k = 0; k < 8; ++k) {
            float af[8], bf[8];
#pragma unroll
            for (int i = 0; i < 8; ++i) af[i] = As[k][ty * 8 + i];
#pragma unroll
            for (int j = 0; j < 8; ++j) bf[j] = Bs[k][tx * 8 + j];
#pragma unroll
            for (int i = 0; i < 8; ++i)
#pragma unroll
                for (int j = 0; j < 8; ++j)
                    acc[i][j] += af[i] * bf[j];
        }
        __syncthreads();
    }

    const int colBase = blockCol * 128 + tx * 8;
    float bv[8];
#pragma unroll
    for (int j = 0; j < 8; ++j) bv[j] = bias[colBase + j];

#pragma unroll
    for (int i = 0; i < 8; ++i) {
        const int row = blockRow * 128 + ty * 8 + i;
        float* crow = out + (size_t)row * N + colBase;
        float4 r0, r1;
        r0.x = acc[i][0] + bv[0]; r0.y = acc[i][1] + bv[1];
        r0.z = acc[i][2] + bv[2]; r0.w = acc[i][3] + bv[3];
        r1.x = acc[i][4] + bv[4]; r1.y = acc[i][5] + bv[5];
        r1.z = acc[i][6] + bv[6]; r1.w = acc[i][7] + bv[7];
        *(float4*)(crow)     = r0;
        *(float4*)(crow + 4) = r1;
    }
}

// ---------------------------------------------------------------------------
// Flash attention (fp32, causal). One block = (b, h, 64-query tile).
// 256 threads. Thread t owns query row t/4; sub = t%4 selects its 16-key
// slice (for S) and its 16-dim slice (for O). Online softmax; row stats
// replicated across each quad via shuffles. Tiles above the diagonal skipped.
// Dynamic smem: Qs,Ks,Vs,Ps each [64][68] floats = 69632 bytes.
// ---------------------------------------------------------------------------
#define ATT_PITCH 68
#define ATT_SMEM  (4 * 64 * ATT_PITCH * 4)

__global__ void __launch_bounds__(256)
attention_kernel()
{
    extern __shared__ float sm[];
    float* Qs = sm;
    float* Ks = sm + 64 * ATT_PITCH;
    float* Vs = sm + 2 * 64 * ATT_PITCH;
    float* Ps = sm + 3 * 64 * ATT_PITCH;

    const int qi = blockIdx.x;           // query tile (0..31)
    const int bh = blockIdx.y;           // 0..31
    const int b  = bh >> 4;
    const int h  = bh & 15;

    const int tid   = threadIdx.x;
    const int r     = tid >> 2;          // load row / owned query row (0..63)
    const int sub   = tid & 3;           // quarter index
    const int cbase = sub * 16;

    const float scale = 0.125f;          // 1/sqrt(64)
    const int qg = qi * 64 + r;          // global query index owned by thread

    // ---- load Q tile ----
    {
        const float* src = g_qkv + ((size_t)(b * SEQ + qi * 64 + r)) * C3 + h * HDIM + cbase;
        float* dst = &Qs[r * ATT_PITCH + cbase];
#pragma unroll
        for (int v = 0; v < 4; ++v)
            *(float4*)(dst + 4 * v) = *(const float4*)(src + 4 * v);
    }

    float o[16];
#pragma unroll
    for (int j = 0; j < 16; ++j) o[j] = 0.f;
    float m_i = -INFINITY;
    float l_i = 0.f;

    for (int kt = 0; kt <= qi; ++kt) {
        __syncthreads();   // previous iteration done with Ks/Vs/Ps (and Q load visible)

        // ---- load K,V tiles (keys kt*64 + r) ----
        {
            const size_t rowOff = ((size_t)(b * SEQ + kt * 64 + r)) * C3 + h * HDIM + cbase;
            const float* ksrc = g_qkv + rowOff + CDIM;       // K block
            const float* vsrc = g_qkv + rowOff + 2 * CDIM;   // V block
            float* kdst = &Ks[r * ATT_PITCH + cbase];
            float* vdst = &Vs[r * ATT_PITCH + cbase];
#pragma unroll
            for (int v = 0; v < 4; ++v) {
                *(float4*)(kdst + 4 * v) = *(const float4*)(ksrc + 4 * v);
                *(float4*)(vdst + 4 * v) = *(const float4*)(vsrc + 4 * v);
            }
        }
        __syncthreads();

        // ---- S = scale * Q K^T for this thread's 16 keys ----
        float s[16];
#pragma unroll
        for (int kk = 0; kk < 16; ++kk) s[kk] = 0.f;

        for (int d0 = 0; d0 < 64; d0 += 4) {
            const float4 q4 = *(const float4*)&Qs[r * ATT_PITCH + d0];
#pragma unroll
            for (int kk = 0; kk < 16; ++kk) {
                const float4 k4 = *(const float4*)&Ks[(cbase + kk) * ATT_PITCH + d0];
                s[kk] += q4.x * k4.x + q4.y * k4.y + q4.z * k4.z + q4.w * k4.w;
            }
        }

        if (kt == qi) {
            // diagonal tile: mask keys beyond the query
#pragma unroll
            for (int kk = 0; kk < 16; ++kk) {
                const int kg = kt * 64 + cbase + kk;
                s[kk] = (kg > qg) ? -INFINITY : s[kk] * scale;
            }
        } else {
#pragma unroll
            for (int kk = 0; kk < 16; ++kk) s[kk] *= scale;
        }

        // ---- online softmax ----
        float mt = s[0];
#pragma unroll
        for (int kk = 1; kk < 16; ++kk) mt = fmaxf(mt, s[kk]);
        mt = fmaxf(mt, __shfl_xor_sync(0xffffffffu, mt, 1));
        mt = fmaxf(mt, __shfl_xor_sync(0xffffffffu, mt, 2));

        const float m_new = fmaxf(m_i, mt);
        const float corr  = __expf(m_i - m_new);   // 0 on first tile (m_i=-inf)

        float lsum = 0.f;
#pragma unroll
        for (int kk = 0; kk < 16; ++kk) {
            const float p = __expf(s[kk] - m_new);
            Ps[r * ATT_PITCH + cbase + kk] = p;
            lsum += p;
        }
        lsum += __shfl_xor_sync(0xffffffffu, lsum, 1);
        lsum += __shfl_xor_sync(0xffffffffu, lsum, 2);

        l_i = l_i * corr + lsum;
        m_i = m_new;
#pragma unroll
        for (int j = 0; j < 16; ++j) o[j] *= corr;

        __syncthreads();   // Ps fully written

        // ---- O += P @ V for this thread's 16 dims ----
        const int dbase = cbase;
        for (int k = 0; k < 64; ++k) {
            const float p = Ps[r * ATT_PITCH + k];
            const float* vrow = &Vs[k * ATT_PITCH + dbase];
            const float4 v0 = *(const float4*)(vrow);
            const float4 v1 = *(const float4*)(vrow + 4);
            const float4 v2 = *(const float4*)(vrow + 8);
            const float4 v3 = *(const float4*)(vrow + 12);
            o[0]  += p * v0.x; o[1]  += p * v0.y; o[2]  += p * v0.z; o[3]  += p * v0.w;
            o[4]  += p * v1.x; o[5]  += p * v1.y; o[6]  += p * v1.z; o[7]  += p * v1.w;
            o[8]  += p * v2.x; o[9]  += p * v2.y; o[10] += p * v2.z; o[11] += p * v2.w;
            o[12] += p * v3.x; o[13] += p * v3.y; o[14] += p * v3.z; o[15] += p * v3.w;
        }
    }

    // ---- normalize and write [B,T,C] layout ----
    const float inv_l = 1.f / l_i;
    float* dst = g_att + ((size_t)(b * SEQ + qg)) * CDIM + h * HDIM + cbase;
#pragma unroll
    for (int v = 0; v < 4; ++v) {
        float4 w;
        w.x = o[4 * v + 0] * inv_l;
        w.y = o[4 * v + 1] * inv_l;
        w.z = o[4 * v + 2] * inv_l;
        w.w = o[4 * v + 3] * inv_l;
        *(float4*)(dst + 4 * v) = w;
    }
}

// ---------------------------------------------------------------------------
// launch
// ---------------------------------------------------------------------------
extern "C" void kernel_launch(void* const* d_in, const int* in_sizes, int n_in,
                              void* d_out, int out_size)
{
    const float* x      = (const float*)d_in[0];
    const float* w_qkv  = (const float*)d_in[1];
    const float* b_qkv  = (const float*)d_in[2];
    const float* w_proj = (const float*)d_in[3];
    const float* b_proj = (const float*)d_in[4];
    float* out = (float*)d_out;

    float* qkv = nullptr;
    float* att = nullptr;
    cudaGetSymbolAddress((void**)&qkv, g_qkv);
    cudaGetSymbolAddress((void**)&att, g_att);

    cudaFuncSetAttribute(attention_kernel,
                         cudaFuncAttributeMaxDynamicSharedMemorySize, ATT_SMEM);

    // 1) qkv = x @ w_qkv + b_qkv        [4096,3072]
    sgemm_bias_kernel<<<dim3(C3 / 128, MROWS / 128), 256>>>(
        x, w_qkv, b_qkv, qkv, MROWS, C3, CDIM);

    // 2) causal flash attention -> g_att [4096,1024]
    attention_kernel<<<dim3(SEQ / 64, BATCH * NHEAD), 256, ATT_SMEM>>>();

    // 3) out = att @ w_proj + b_proj    [4096,1024]
    sgemm_bias_kernel<<<dim3(CDIM / 128, MROWS / 128), 256>>>(
        att, w_proj, b_proj, out, MROWS, CDIM, CDIM);
}

// round 3
// speedup vs baseline: 2.9768x; 2.9768x over previous
#include <cuda_runtime.h>
#include <math.h>

// Problem constants
#define BATCH   2
#define SEQ     2048
#define CDIM    1024
#define NHEAD   16
#define HDIM    64
#define C3      3072
#define MROWS   4096            // BATCH*SEQ

// Scratch (device globals — no runtime allocation allowed)
__device__ float g_qkv[MROWS * C3];    // [4096, 3072]
__device__ float g_att[MROWS * CDIM];  // [4096, 1024]

// ---------------------------------------------------------------------------
// Classic 128x128x8 SGEMM with bias: out[M,N] = A[M,K] @ W[K,N] + bias[N]
// 256 threads, 8x8 accumulators per thread.
// ---------------------------------------------------------------------------
__global__ void __launch_bounds__(256)
sgemm_bias_kernel(const float* __restrict__ A, const float* __restrict__ W,
                  const float* __restrict__ bias, float* __restrict__ out,
                  int M, int N, int K)
{
    __shared__ float As[8][128];
    __shared__ float Bs[8][128];

    const int tid = threadIdx.x;
    const int blockRow = blockIdx.y;
    const int blockCol = blockIdx.x;

    const int aRow = tid >> 1;
    const int aCol = (tid & 1) * 4;
    const int bRow = tid >> 5;
    const int bCol = (tid & 31) * 4;

    const float* Aptr = A + (size_t)(blockRow * 128 + aRow) * K + aCol;
    const float* Wptr = W + (size_t)bRow * N + blockCol * 128 + bCol;

    const int ty = tid >> 4;
    const int tx = tid & 15;

    float acc[8][8];
#pragma unroll
    for (int i = 0; i < 8; ++i)
#pragma unroll
        for (int j = 0; j < 8; ++j) acc[i][j] = 0.f;

    for (int kt = 0; kt < K; kt += 8) {
        float4 a4 = *(const float4*)Aptr;  Aptr += 8;
        float4 b4 = *(const float4*)Wptr;  Wptr += (size_t)8 * N;

        As[aCol + 0][aRow] = a4.x;
        As[aCol + 1][aRow] = a4.y;
        As[aCol + 2][aRow] = a4.z;
        As[aCol + 3][aRow] = a4.w;
        *(float4*)&Bs[bRow][bCol] = b4;
        __syncthreads();

#pragma unroll
        for (int k = 0; k < 8; ++k) {
            float af[8], bf[8];
#pragma unroll
            for (int i = 0; i < 8; ++i) af[i] = As[k][ty * 8 + i];
#pragma unroll
            for (int j = 0; j < 8; ++j) bf[j] = Bs[k][tx * 8 + j];
#pragma unroll
            for (int i = 0; i < 8; ++i)
#pragma unroll
                for (int j = 0; j < 8; ++j)
                    acc[i][j] += af[i] * bf[j];
        }
        __syncthreads();
    }

    const int colBase = blockCol * 128 + tx * 8;
    float bv[8];
#pragma unroll
    for (int j = 0; j < 8; ++j) bv[j] = bias[colBase + j];

#pragma unroll
    for (int i = 0; i < 8; ++i) {
        const int row = blockRow * 128 + ty * 8 + i;
        float* crow = out + (size_t)row * N + colBase;
        float4 r0, r1;
        r0.x = acc[i][0] + bv[0]; r0.y = acc[i][1] + bv[1];
        r0.z = acc[i][2] + bv[2]; r0.w = acc[i][3] + bv[3];
        r1.x = acc[i][4] + bv[4]; r1.y = acc[i][5] + bv[5];
        r1.z = acc[i][6] + bv[6]; r1.w = acc[i][7] + bv[7];
        *(float4*)(crow)     = r0;
        *(float4*)(crow + 4) = r1;
    }
}

// ---------------------------------------------------------------------------
// Flash attention (fp32, causal) — GEMM-shaped.
// Block = (b, h, 64-query tile). 256 threads = 16x16; each thread owns a
// 4x4 register tile for S (q x k) and for O (q x d), computed as outer
// products (2 LDS.128 -> 16 FMA per step).
// Layouts in smem (pitch 68 floats):
//   Qs[d][q], Ks[d][k]  (transposed on load)   -> S phase
//   Vs[k][d]  (natural)                        -> O phase
//   Pts[k][q] (P transposed on store)          -> O phase
// Online softmax: only row-max reduced per tile (16-lane shuffles);
// row-sum l kept as per-thread partials, reduced once at the end.
// ---------------------------------------------------------------------------
#define APITCH 68
#define ATT_SMEM (4 * 64 * APITCH * 4)

__global__ void __launch_bounds__(256, 2)
attention_kernel()
{
    extern __shared__ float sm[];
    float* Qs  = sm;
    float* Ks  = sm + 64 * APITCH;
    float* Vs  = sm + 2 * 64 * APITCH;
    float* Pts = sm + 3 * 64 * APITCH;

    const int qi = gridDim.x - 1 - blockIdx.x;   // heavy tiles first
    const int bh = blockIdx.y;
    const int b  = bh >> 4;
    const int h  = bh & 15;

    const int tid = threadIdx.x;
    const int ty  = tid >> 4;            // 0..15 (query group)
    const int tx  = tid & 15;            // 0..15 (key / dim group)

    // loader mapping: each thread loads 16 dims of one token
    const int lr    = tid >> 2;          // token row 0..63
    const int lsub  = tid & 3;
    const int lbase = lsub * 16;

    const float scale = 0.125f;

    // ---- load Q tile, transposed: Qs[d][q] ----
    {
        const float* src = g_qkv + ((size_t)(b * SEQ + qi * 64 + lr)) * C3 + h * HDIM + lbase;
        float tmp[16];
#pragma unroll
        for (int v = 0; v < 4; ++v)
            *(float4*)&tmp[4 * v] = *(const float4*)(src + 4 * v);
#pragma unroll
        for (int kk = 0; kk < 16; ++kk)
            Qs[(lbase + kk) * APITCH + lr] = tmp[kk];
    }

    float o[4][4];
#pragma unroll
    for (int i = 0; i < 4; ++i)
#pragma unroll
        for (int j = 0; j < 4; ++j) o[i][j] = 0.f;
    float m_i[4], l_i[4];
#pragma unroll
    for (int i = 0; i < 4; ++i) { m_i[i] = -INFINITY; l_i[i] = 0.f; }

    for (int kt = 0; kt <= qi; ++kt) {
        __syncthreads();   // prev iter done reading Ks/Vs/Pts (and Q visible)

        // ---- load K (transposed -> Ks[d][k]) and V (natural -> Vs[k][d]) ----
        {
            const size_t rowOff = ((size_t)(b * SEQ + kt * 64 + lr)) * C3 + h * HDIM + lbase;
            const float* ksrc = g_qkv + rowOff + CDIM;
            const float* vsrc = g_qkv + rowOff + 2 * CDIM;
            float ktmp[16];
#pragma unroll
            for (int v = 0; v < 4; ++v)
                *(float4*)&ktmp[4 * v] = *(const float4*)(ksrc + 4 * v);
#pragma unroll
            for (int kk = 0; kk < 16; ++kk)
                Ks[(lbase + kk) * APITCH + lr] = ktmp[kk];
            float* vdst = &Vs[lr * APITCH + lbase];
#pragma unroll
            for (int v = 0; v < 4; ++v)
                *(float4*)(vdst + 4 * v) = *(const float4*)(vsrc + 4 * v);
        }
        __syncthreads();

        // ---- S = Q^T K outer-product accumulation ----
        float s[4][4];
#pragma unroll
        for (int i = 0; i < 4; ++i)
#pragma unroll
            for (int j = 0; j < 4; ++j) s[i][j] = 0.f;

#pragma unroll 8
        for (int d = 0; d < 64; ++d) {
            const float4 q4 = *(const float4*)&Qs[d * APITCH + ty * 4];
            const float4 k4 = *(const float4*)&Ks[d * APITCH + tx * 4];
            s[0][0] += q4.x * k4.x; s[0][1] += q4.x * k4.y; s[0][2] += q4.x * k4.z; s[0][3] += q4.x * k4.w;
            s[1][0] += q4.y * k4.x; s[1][1] += q4.y * k4.y; s[1][2] += q4.y * k4.z; s[1][3] += q4.y * k4.w;
            s[2][0] += q4.z * k4.x; s[2][1] += q4.z * k4.y; s[2][2] += q4.z * k4.z; s[2][3] += q4.z * k4.w;
            s[3][0] += q4.w * k4.x; s[3][1] += q4.w * k4.y; s[3][2] += q4.w * k4.z; s[3][3] += q4.w * k4.w;
        }

        if (kt == qi) {
            // diagonal tile: mask keys beyond the query
#pragma unroll
            for (int i = 0; i < 4; ++i) {
                const int qg = qi * 64 + ty * 4 + i;
#pragma unroll
                for (int j = 0; j < 4; ++j) {
                    const int kg = kt * 64 + tx * 4 + j;
                    s[i][j] = (kg > qg) ? -INFINITY : s[i][j] * scale;
                }
            }
        } else {
#pragma unroll
            for (int i = 0; i < 4; ++i)
#pragma unroll
                for (int j = 0; j < 4; ++j) s[i][j] *= scale;
        }

        // ---- online softmax (row max reduced across the 16-lane tx group) ----
#pragma unroll
        for (int i = 0; i < 4; ++i) {
            float mt = fmaxf(fmaxf(s[i][0], s[i][1]), fmaxf(s[i][2], s[i][3]));
            mt = fmaxf(mt, __shfl_xor_sync(0xffffffffu, mt, 1));
            mt = fmaxf(mt, __shfl_xor_sync(0xffffffffu, mt, 2));
            mt = fmaxf(mt, __shfl_xor_sync(0xffffffffu, mt, 4));
            mt = fmaxf(mt, __shfl_xor_sync(0xffffffffu, mt, 8));

            const float mn   = fmaxf(m_i[i], mt);
            const float corr = __expf(m_i[i] - mn);   // 0 on first tile
            m_i[i] = mn;
            l_i[i] *= corr;
            o[i][0] *= corr; o[i][1] *= corr; o[i][2] *= corr; o[i][3] *= corr;

            float ls = 0.f;
#pragma unroll
            for (int j = 0; j < 4; ++j) {
                const float p = __expf(s[i][j] - mn);
                Pts[(tx * 4 + j) * APITCH + ty * 4 + i] = p;
                ls += p;
            }
            l_i[i] += ls;   // per-thread partial; reduced at the end
        }
        __syncthreads();   // Pts fully written

        // ---- O += P V outer-product accumulation ----
#pragma unroll 8
        for (int k = 0; k < 64; ++k) {
            const float4 p4 = *(const float4*)&Pts[k * APITCH + ty * 4];
            const float4 v4 = *(const float4*)&Vs[k * APITCH + tx * 4];
            o[0][0] += p4.x * v4.x; o[0][1] += p4.x * v4.y; o[0][2] += p4.x * v4.z; o[0][3] += p4.x * v4.w;
            o[1][0] += p4.y * v4.x; o[1][1] += p4.y * v4.y; o[1][2] += p4.y * v4.z; o[1][3] += p4.y * v4.w;
            o[2][0] += p4.z * v4.x; o[2][1] += p4.z * v4.y; o[2][2] += p4.z * v4.z; o[2][3] += p4.z * v4.w;
            o[3][0] += p4.w * v4.x; o[3][1] += p4.w * v4.y; o[3][2] += p4.w * v4.z; o[3][3] += p4.w * v4.w;
        }
    }

    // ---- final l reduction across tx group, normalize, store ----
#pragma unroll
    for (int i = 0; i < 4; ++i) {
        float l = l_i[i];
        l += __shfl_xor_sync(0xffffffffu, l, 1);
        l += __shfl_xor_sync(0xffffffffu, l, 2);
        l += __shfl_xor_sync(0xffffffffu, l, 4);
        l += __shfl_xor_sync(0xffffffffu, l, 8);
        const float inv_l = 1.f / l;

        const int q = qi * 64 + ty * 4 + i;
        float* dst = g_att + ((size_t)(b * SEQ + q)) * CDIM + h * HDIM + tx * 4;
        float4 w;
        w.x = o[i][0] * inv_l; w.y = o[i][1] * inv_l;
        w.z = o[i][2] * inv_l; w.w = o[i][3] * inv_l;
        *(float4*)dst = w;
    }
}

// ---------------------------------------------------------------------------
// launch
// ---------------------------------------------------------------------------
extern "C" void kernel_launch(void* const* d_in, const int* in_sizes, int n_in,
                              void* d_out, int out_size)
{
    const float* x      = (const float*)d_in[0];
    const float* w_qkv  = (const float*)d_in[1];
    const float* b_qkv  = (const float*)d_in[2];
    const float* w_proj = (const float*)d_in[3];
    const float* b_proj = (const float*)d_in[4];
    float* out = (float*)d_out;

    float* qkv = nullptr;
    float* att = nullptr;
    cudaGetSymbolAddress((void**)&qkv, g_qkv);
    cudaGetSymbolAddress((void**)&att, g_att);

    cudaFuncSetAttribute(attention_kernel,
                         cudaFuncAttributeMaxDynamicSharedMemorySize, ATT_SMEM);

    // 1) qkv = x @ w_qkv + b_qkv        [4096,3072]
    sgemm_bias_kernel<<<dim3(C3 / 128, MROWS / 128), 256>>>(
        x, w_qkv, b_qkv, qkv, MROWS, C3, CDIM);

    // 2) causal flash attention -> g_att [4096,1024]
    attention_kernel<<<dim3(SEQ / 64, BATCH * NHEAD), 256, ATT_SMEM>>>();

    // 3) out = att @ w_proj + b_proj    [4096,1024]
    sgemm_bias_kernel<<<dim3(CDIM / 128, MROWS / 128), 256>>>(
        att, w_proj, b_proj, out, MROWS, CDIM, CDIM);
}

// round 5
// speedup vs baseline: 4.7295x; 1.5888x over previous
#include <cuda_runtime.h>
#include <cuda_bf16.h>
#include <math.h>
#include <stdint.h>

// Problem constants
#define BATCH   2
#define SEQ     2048
#define CDIM    1024
#define NHEAD   16
#define HDIM    64
#define C3      3072
#define MROWS   4096            // BATCH*SEQ
#define KEFF    3072            // split-bf16 effective K (= 3*CDIM)
#define NCHUNK  48              // KEFF / 64

// Scratch (device globals — no runtime allocation allowed)
__device__ float g_qkv[MROWS * C3];                    // [4096, 3072] fp32
__device__ float g_att[MROWS * CDIM];                  // [4096, 1024] fp32
__device__ __nv_bfloat16 g_abig[MROWS * KEFF];         // split A: [hi | lo | hi]
__device__ __nv_bfloat16 g_wqkvt[C3 * KEFF];           // W_qkv^T split: [hi | hi | lo]
__device__ __nv_bfloat16 g_wprojt[CDIM * KEFF];        // W_proj^T split: [hi | hi | lo]

// ---------------------------------------------------------------------------
// Helpers (all base-sm_100-legal PTX: cp.async, ldmatrix, mma.sync bf16)
// ---------------------------------------------------------------------------
__device__ __forceinline__ uint32_t smem_u32(const void* p) {
    uint32_t a;
    asm("{ .reg .u64 t; cvta.to.shared.u64 t, %1; cvt.u32.u64 %0, t; }" : "=r"(a) : "l"(p));
    return a;
}
__device__ __forceinline__ void cp_async16(uint32_t dst, const void* src) {
    asm volatile("cp.async.cg.shared.global [%0], [%1], 16;" :: "r"(dst), "l"(src));
}
#define CP_COMMIT()  asm volatile("cp.async.commit_group;")
#define CP_WAIT(n)   asm volatile("cp.async.wait_group %0;" :: "n"(n))

__device__ __forceinline__ void ldmx4(uint32_t* r, uint32_t addr) {
    asm volatile("ldmatrix.sync.aligned.m8n8.x4.shared.b16 {%0,%1,%2,%3}, [%4];"
                 : "=r"(r[0]), "=r"(r[1]), "=r"(r[2]), "=r"(r[3]) : "r"(addr));
}
__device__ __forceinline__ void mma16816(float* d, const uint32_t* a, const uint32_t* b) {
    asm volatile("mma.sync.aligned.m16n8k16.row.col.f32.bf16.bf16.f32 "
                 "{%0,%1,%2,%3}, {%4,%5,%6,%7}, {%8,%9}, {%0,%1,%2,%3};"
                 : "+f"(d[0]), "+f"(d[1]), "+f"(d[2]), "+f"(d[3])
                 : "r"(a[0]), "r"(a[1]), "r"(a[2]), "r"(a[3]), "r"(b[0]), "r"(b[1]));
}
#define SWZ(o) ((o) ^ (((o) >> 3) & 0x70))

// ---------------------------------------------------------------------------
// Conversion: fp32 [M][1024] -> split bf16 [M][3072] = [hi | lo | hi]  (A side)
// ---------------------------------------------------------------------------
__global__ void __launch_bounds__(256)
conv_split_kernel(const float* __restrict__ in, __nv_bfloat16* __restrict__ out)
{
    const int idx = blockIdx.x * 256 + threadIdx.x;  // over MROWS*CDIM
    const int m = idx >> 10;
    const int k = idx & 1023;
    const float a = in[idx];
    const __nv_bfloat16 hi = __float2bfloat16(a);
    const __nv_bfloat16 lo = __float2bfloat16(a - __bfloat162float(hi));
    __nv_bfloat16* row = out + (size_t)m * KEFF;
    row[k]            = hi;
    row[CDIM + k]     = lo;
    row[2 * CDIM + k] = hi;
}

// ---------------------------------------------------------------------------
// Weight transpose + split: w [1024][Nw] fp32 -> out [Nw][3072] = [hi | hi | lo]
// so that A.B segments give hi*hi + lo*hi + hi*lo.
// ---------------------------------------------------------------------------
__global__ void __launch_bounds__(1024)
conv_wt_kernel(const float* __restrict__ w, __nv_bfloat16* __restrict__ out, int Nw)
{
    __shared__ float tile[32][33];
    const int n0 = blockIdx.x * 32;
    const int k0 = blockIdx.y * 32;
    tile[threadIdx.y][threadIdx.x] = w[(size_t)(k0 + threadIdx.y) * Nw + n0 + threadIdx.x];
    __syncthreads();
    const int n = n0 + threadIdx.y;
    const int k = k0 + threadIdx.x;
    const float a = tile[threadIdx.x][threadIdx.y];
    const __nv_bfloat16 hi = __float2bfloat16(a);
    const __nv_bfloat16 lo = __float2bfloat16(a - __bfloat162float(hi));
    __nv_bfloat16* row = out + (size_t)n * KEFF;
    row[k]            = hi;
    row[CDIM + k]     = hi;
    row[2 * CDIM + k] = lo;
}

// ---------------------------------------------------------------------------
// Tensor-core bf16 GEMM (mma.sync): out[M][Nout] = A[M][KEFF] * Bt[Nout][KEFF] + bias
// CTA: 128x128 tile, 256 threads = 8 warps (2 along M x 4 along N).
// Warp: 64x32 = 4x4 grid of m16n8 mma tiles, k16 steps.
// K chunks of 64 bf16 (128B rows, SW128 swizzle), cp.async double buffer.
// ---------------------------------------------------------------------------
#define GEMM_DYN_SMEM (2 * 32768)   // 2 stages x (A 16KB + B 16KB)

__global__ void __launch_bounds__(256, 2)
gemm_mma_kernel(const __nv_bfloat16* __restrict__ A, const __nv_bfloat16* __restrict__ Bt,
                const float* __restrict__ bias, float* __restrict__ out, int Nout)
{
    extern __shared__ __align__(1024) char dyn[];
    const uint32_t tiles = smem_u32(dyn);

    const int tid = threadIdx.x;
    const int wid = tid >> 5;
    const int lane = tid & 31;
    const int wm = wid & 1;              // 0..1  -> 64-row slab
    const int wn = wid >> 1;             // 0..3  -> 32-col slab
    const int m0 = blockIdx.y * 128;
    const int n0 = blockIdx.x * 128;

    const __nv_bfloat16* Arow = A  + (size_t)m0 * KEFF;
    const __nv_bfloat16* Brow = Bt + (size_t)n0 * KEFF;

    // chunk loader: A tile [128][64] + B tile [128][64] bf16, SW128 rows (128B)
    auto load_chunk = [&](int c, int buf) {
        const uint32_t abase = tiles + buf * 32768;
        const uint32_t bbase = abase + 16384;
        const __nv_bfloat16* ag = Arow + c * 64;
        const __nv_bfloat16* bg = Brow + c * 64;
#pragma unroll
        for (int i = 0; i < 4; ++i) {
            const int g   = tid + 256 * i;      // 0..1023
            const int row = g >> 3;
            const int gc  = g & 7;
            const uint32_t off = SWZ((uint32_t)(row * 128 + gc * 16));
            cp_async16(abase + off, (const char*)(ag + (size_t)row * KEFF) + gc * 16);
            cp_async16(bbase + off, (const char*)(bg + (size_t)row * KEFF) + gc * 16);
        }
        CP_COMMIT();
    };

    float acc[4][4][4];
#pragma unroll
    for (int mi = 0; mi < 4; ++mi)
#pragma unroll
        for (int ni = 0; ni < 4; ++ni)
#pragma unroll
            for (int r = 0; r < 4; ++r) acc[mi][ni][r] = 0.f;

    // precomputed ldmatrix lane address components
    const int l15 = lane & 15;
    const int lhi16 = (lane >> 4) * 16;          // A: +16B for k upper half
    const int b_row = ((lane & 16) >> 1) + (lane & 7);   // 0..7 / 8..15 row-in-16
    const int b_khalf = (lane & 8) ? 16 : 0;     // B: +16B for k upper half

    load_chunk(0, 0);

    for (int c = 0; c < NCHUNK; ++c) {
        const int b = c & 1;
        if (c + 1 < NCHUNK) {
            load_chunk(c + 1, 1 - b);
            CP_WAIT(1);
        } else {
            CP_WAIT(0);
        }
        __syncthreads();

        const uint32_t abase = tiles + b * 32768;
        const uint32_t bbase = abase + 16384;

#pragma unroll
        for (int ks = 0; ks < 4; ++ks) {
            const int kb = ks * 32;
            uint32_t afr[4][4];
#pragma unroll
            for (int mi = 0; mi < 4; ++mi) {
                const int row = wm * 64 + mi * 16 + l15;
                ldmx4(afr[mi], abase + SWZ((uint32_t)(row * 128 + kb + lhi16)));
            }
            uint32_t bfr[2][4];
#pragma unroll
            for (int nj = 0; nj < 2; ++nj) {
                const int row = wn * 32 + nj * 16 + b_row;
                ldmx4(bfr[nj], bbase + SWZ((uint32_t)(row * 128 + kb + b_khalf)));
            }
#pragma unroll
            for (int mi = 0; mi < 4; ++mi) {
#pragma unroll
                for (int ni = 0; ni < 4; ++ni)
                    mma16816(acc[mi][ni], afr[mi], &bfr[ni >> 1][(ni & 1) * 2]);
            }
        }
        __syncthreads();
    }

    // epilogue: D fragment (row t/4 & +8, cols 2*(t%4)+{0,1}) + bias
    const int tr = lane >> 2;
    const int tc = (lane & 3) * 2;
#pragma unroll
    for (int mi = 0; mi < 4; ++mi) {
#pragma unroll
        for (int ni = 0; ni < 4; ++ni) {
            const int gr = m0 + wm * 64 + mi * 16 + tr;
            const int gc = n0 + wn * 32 + ni * 8 + tc;
            const float b0 = bias[gc], b1 = bias[gc + 1];
            float2 v0 = make_float2(acc[mi][ni][0] + b0, acc[mi][ni][1] + b1);
            float2 v1 = make_float2(acc[mi][ni][2] + b0, acc[mi][ni][3] + b1);
            *(float2*)(out + (size_t)gr * Nout + gc)       = v0;
            *(float2*)(out + (size_t)(gr + 8) * Nout + gc) = v1;
        }
    }
}

// ---------------------------------------------------------------------------
// Flash attention (fp32, causal) — GEMM-shaped (unchanged from R3, ~715us)
// ---------------------------------------------------------------------------
#define APITCH 68
#define ATT_SMEM (4 * 64 * APITCH * 4)

__global__ void __launch_bounds__(256, 2)
attention_kernel()
{
    extern __shared__ float sm[];
    float* Qs  = sm;
    float* Ks  = sm + 64 * APITCH;
    float* Vs  = sm + 2 * 64 * APITCH;
    float* Pts = sm + 3 * 64 * APITCH;

    const int qi = gridDim.x - 1 - blockIdx.x;   // heavy tiles first
    const int bh = blockIdx.y;
    const int b  = bh >> 4;
    const int h  = bh & 15;

    const int tid = threadIdx.x;
    const int ty  = tid >> 4;
    const int tx  = tid & 15;

    const int lr    = tid >> 2;
    const int lbase = (tid & 3) * 16;

    const float scale = 0.125f;

    {
        const float* src = g_qkv + ((size_t)(b * SEQ + qi * 64 + lr)) * C3 + h * HDIM + lbase;
        float tmp[16];
#pragma unroll
        for (int v = 0; v < 4; ++v)
            *(float4*)&tmp[4 * v] = *(const float4*)(src + 4 * v);
#pragma unroll
        for (int kk = 0; kk < 16; ++kk)
            Qs[(lbase + kk) * APITCH + lr] = tmp[kk];
    }

    float o[4][4];
#pragma unroll
    for (int i = 0; i < 4; ++i)
#pragma unroll
        for (int j = 0; j < 4; ++j) o[i][j] = 0.f;
    float m_i[4], l_i[4];
#pragma unroll
    for (int i = 0; i < 4; ++i) { m_i[i] = -INFINITY; l_i[i] = 0.f; }

    for (int kt = 0; kt <= qi; ++kt) {
        __syncthreads();

        {
            const size_t rowOff = ((size_t)(b * SEQ + kt * 64 + lr)) * C3 + h * HDIM + lbase;
            const float* ksrc = g_qkv + rowOff + CDIM;
            const float* vsrc = g_qkv + rowOff + 2 * CDIM;
            float ktmp[16];
#pragma unroll
            for (int v = 0; v < 4; ++v)
                *(float4*)&ktmp[4 * v] = *(const float4*)(ksrc + 4 * v);
#pragma unroll
            for (int kk = 0; kk < 16; ++kk)
                Ks[(lbase + kk) * APITCH + lr] = ktmp[kk];
            float* vdst = &Vs[lr * APITCH + lbase];
#pragma unroll
            for (int v = 0; v < 4; ++v)
                *(float4*)(vdst + 4 * v) = *(const float4*)(vsrc + 4 * v);
        }
        __syncthreads();

        float s[4][4];
#pragma unroll
        for (int i = 0; i < 4; ++i)
#pragma unroll
            for (int j = 0; j < 4; ++j) s[i][j] = 0.f;

#pragma unroll 8
        for (int d = 0; d < 64; ++d) {
            const float4 q4 = *(const float4*)&Qs[d * APITCH + ty * 4];
            const float4 k4 = *(const float4*)&Ks[d * APITCH + tx * 4];
            s[0][0] += q4.x * k4.x; s[0][1] += q4.x * k4.y; s[0][2] += q4.x * k4.z; s[0][3] += q4.x * k4.w;
            s[1][0] += q4.y * k4.x; s[1][1] += q4.y * k4.y; s[1][2] += q4.y * k4.z; s[1][3] += q4.y * k4.w;
            s[2][0] += q4.z * k4.x; s[2][1] += q4.z * k4.y; s[2][2] += q4.z * k4.z; s[2][3] += q4.z * k4.w;
            s[3][0] += q4.w * k4.x; s[3][1] += q4.w * k4.y; s[3][2] += q4.w * k4.z; s[3][3] += q4.w * k4.w;
        }

        if (kt == qi) {
#pragma unroll
            for (int i = 0; i < 4; ++i) {
                const int qg = qi * 64 + ty * 4 + i;
#pragma unroll
                for (int j = 0; j < 4; ++j) {
                    const int kg = kt * 64 + tx * 4 + j;
                    s[i][j] = (kg > qg) ? -INFINITY : s[i][j] * scale;
                }
            }
        } else {
#pragma unroll
            for (int i = 0; i < 4; ++i)
#pragma unroll
                for (int j = 0; j < 4; ++j) s[i][j] *= scale;
        }

#pragma unroll
        for (int i = 0; i < 4; ++i) {
            float mt = fmaxf(fmaxf(s[i][0], s[i][1]), fmaxf(s[i][2], s[i][3]));
            mt = fmaxf(mt, __shfl_xor_sync(0xffffffffu, mt, 1));
            mt = fmaxf(mt, __shfl_xor_sync(0xffffffffu, mt, 2));
            mt = fmaxf(mt, __shfl_xor_sync(0xffffffffu, mt, 4));
            mt = fmaxf(mt, __shfl_xor_sync(0xffffffffu, mt, 8));

            const float mn   = fmaxf(m_i[i], mt);
            const float corr = __expf(m_i[i] - mn);
            m_i[i] = mn;
            l_i[i] *= corr;
            o[i][0] *= corr; o[i][1] *= corr; o[i][2] *= corr; o[i][3] *= corr;

            float ls = 0.f;
#pragma unroll
            for (int j = 0; j < 4; ++j) {
                const float p = __expf(s[i][j] - mn);
                Pts[(tx * 4 + j) * APITCH + ty * 4 + i] = p;
                ls += p;
            }
            l_i[i] += ls;
        }
        __syncthreads();

#pragma unroll 8
        for (int k = 0; k < 64; ++k) {
            const float4 p4 = *(const float4*)&Pts[k * APITCH + ty * 4];
            const float4 v4 = *(const float4*)&Vs[k * APITCH + tx * 4];
            o[0][0] += p4.x * v4.x; o[0][1] += p4.x * v4.y; o[0][2] += p4.x * v4.z; o[0][3] += p4.x * v4.w;
            o[1][0] += p4.y * v4.x; o[1][1] += p4.y * v4.y; o[1][2] += p4.y * v4.z; o[1][3] += p4.y * v4.w;
            o[2][0] += p4.z * v4.x; o[2][1] += p4.z * v4.y; o[2][2] += p4.z * v4.z; o[2][3] += p4.z * v4.w;
            o[3][0] += p4.w * v4.x; o[3][1] += p4.w * v4.y; o[3][2] += p4.w * v4.z; o[3][3] += p4.w * v4.w;
        }
    }

#pragma unroll
    for (int i = 0; i < 4; ++i) {
        float l = l_i[i];
        l += __shfl_xor_sync(0xffffffffu, l, 1);
        l += __shfl_xor_sync(0xffffffffu, l, 2);
        l += __shfl_xor_sync(0xffffffffu, l, 4);
        l += __shfl_xor_sync(0xffffffffu, l, 8);
        const float inv_l = 1.f / l;

        const int q = qi * 64 + ty * 4 + i;
        float* dst = g_att + ((size_t)(b * SEQ + q)) * CDIM + h * HDIM + tx * 4;
        float4 w;
        w.x = o[i][0] * inv_l; w.y = o[i][1] * inv_l;
        w.z = o[i][2] * inv_l; w.w = o[i][3] * inv_l;
        *(float4*)dst = w;
    }
}

// ---------------------------------------------------------------------------
// launch
// ---------------------------------------------------------------------------
extern "C" void kernel_launch(void* const* d_in, const int* in_sizes, int n_in,
                              void* d_out, int out_size)
{
    const float* x      = (const float*)d_in[0];
    const float* w_qkv  = (const float*)d_in[1];
    const float* b_qkv  = (const float*)d_in[2];
    const float* w_proj = (const float*)d_in[3];
    const float* b_proj = (const float*)d_in[4];
    float* out = (float*)d_out;

    float* qkv = nullptr;  float* att = nullptr;
    __nv_bfloat16* abig = nullptr; __nv_bfloat16* wqkvt = nullptr; __nv_bfloat16* wprojt = nullptr;
    cudaGetSymbolAddress((void**)&qkv,    g_qkv);
    cudaGetSymbolAddress((void**)&att,    g_att);
    cudaGetSymbolAddress((void**)&abig,   g_abig);
    cudaGetSymbolAddress((void**)&wqkvt,  g_wqkvt);
    cudaGetSymbolAddress((void**)&wprojt, g_wprojt);

    cudaFuncSetAttribute(attention_kernel,
                         cudaFuncAttributeMaxDynamicSharedMemorySize, ATT_SMEM);
    cudaFuncSetAttribute(gemm_mma_kernel,
                         cudaFuncAttributeMaxDynamicSharedMemorySize, GEMM_DYN_SMEM);

    // weight prep (depends only on inputs)
    conv_wt_kernel<<<dim3(C3 / 32, CDIM / 32), dim3(32, 32)>>>(w_qkv, wqkvt, C3);
    conv_wt_kernel<<<dim3(CDIM / 32, CDIM / 32), dim3(32, 32)>>>(w_proj, wprojt, CDIM);

    // 1) x -> split bf16, then qkv = x @ w_qkv + b_qkv (tensor cores)
    conv_split_kernel<<<(MROWS * CDIM) / 256, 256>>>(x, abig);
    gemm_mma_kernel<<<dim3(C3 / 128, MROWS / 128), 256, GEMM_DYN_SMEM>>>(
        abig, wqkvt, b_qkv, qkv, C3);

    // 2) causal flash attention -> g_att
    attention_kernel<<<dim3(SEQ / 64, BATCH * NHEAD), 256, ATT_SMEM>>>();

    // 3) att -> split bf16, then out = att @ w_proj + b_proj (tensor cores)
    conv_split_kernel<<<(MROWS * CDIM) / 256, 256>>>(att, abig);
    gemm_mma_kernel<<<dim3(CDIM / 128, MROWS / 128), 256, GEMM_DYN_SMEM>>>(
        abig, wprojt, b_proj, out, CDIM);
}

// round 6
// speedup vs baseline: 8.7711x; 1.8546x over previous
#include <cuda_runtime.h>
#include <cuda_bf16.h>
#include <math.h>
#include <stdint.h>

// Problem constants
#define BATCH   2
#define SEQ     2048
#define CDIM    1024
#define NHEAD   16
#define HDIM    64
#define C3      3072
#define MROWS   4096            // BATCH*SEQ
#define KEFF    3072            // split-bf16 effective K (= 3*CDIM)
#define NCHUNK  48              // KEFF / 64
#define NBH     32              // BATCH*NHEAD

// Scratch (device globals — no runtime allocation allowed)
__device__ float g_qkv[MROWS * C3];                    // [4096, 3072] fp32
__device__ __nv_bfloat16 g_abig[MROWS * KEFF];         // split A: [hi | lo | hi]
__device__ __nv_bfloat16 g_wqkvt[C3 * KEFF];           // W_qkv^T split: [hi | hi | lo]
__device__ __nv_bfloat16 g_wprojt[CDIM * KEFF];        // W_proj^T split: [hi | hi | lo]
// per-head split attention operands
__device__ __nv_bfloat16 g_q[NBH * 2 * SEQ * HDIM];    // [bh][hi/lo][t][d]
__device__ __nv_bfloat16 g_k[NBH * 2 * SEQ * HDIM];    // [bh][hi/lo][t][d]
__device__ __nv_bfloat16 g_vt[NBH * 2 * HDIM * SEQ];   // [bh][hi/lo][d][t]

// ---------------------------------------------------------------------------
// Helpers (base-sm_100-legal PTX only)
// ---------------------------------------------------------------------------
__device__ __forceinline__ uint32_t smem_u32(const void* p) {
    uint32_t a;
    asm("{ .reg .u64 t; cvta.to.shared.u64 t, %1; cvt.u32.u64 %0, t; }" : "=r"(a) : "l"(p));
    return a;
}
__device__ __forceinline__ void cp_async16(uint32_t dst, const void* src) {
    asm volatile("cp.async.cg.shared.global [%0], [%1], 16;" :: "r"(dst), "l"(src));
}
#define CP_COMMIT()  asm volatile("cp.async.commit_group;")
#define CP_WAIT(n)   asm volatile("cp.async.wait_group %0;" :: "n"(n))

__device__ __forceinline__ void ldmx4(uint32_t* r, uint32_t addr) {
    asm volatile("ldmatrix.sync.aligned.m8n8.x4.shared.b16 {%0,%1,%2,%3}, [%4];"
                 : "=r"(r[0]), "=r"(r[1]), "=r"(r[2]), "=r"(r[3]) : "r"(addr));
}
__device__ __forceinline__ void mma16816(float* d, const uint32_t* a, const uint32_t* b) {
    asm volatile("mma.sync.aligned.m16n8k16.row.col.f32.bf16.bf16.f32 "
                 "{%0,%1,%2,%3}, {%4,%5,%6,%7}, {%8,%9}, {%0,%1,%2,%3};"
                 : "+f"(d[0]), "+f"(d[1]), "+f"(d[2]), "+f"(d[3])
                 : "r"(a[0]), "r"(a[1]), "r"(a[2]), "r"(a[3]), "r"(b[0]), "r"(b[1]));
}
#define SWZ(o) ((o) ^ (((o) >> 3) & 0x70))

// ---------------------------------------------------------------------------
// fp32 [M][1024] -> split bf16 [M][3072] = [hi | lo | hi]  (GEMM A side)
// ---------------------------------------------------------------------------
__global__ void __launch_bounds__(256)
conv_split_kernel(const float* __restrict__ in, __nv_bfloat16* __restrict__ out)
{
    const int idx = blockIdx.x * 256 + threadIdx.x;
    const int m = idx >> 10;
    const int k = idx & 1023;
    const float a = in[idx];
    const __nv_bfloat16 hi = __float2bfloat16(a);
    const __nv_bfloat16 lo = __float2bfloat16(a - __bfloat162float(hi));
    __nv_bfloat16* row = out + (size_t)m * KEFF;
    row[k]            = hi;
    row[CDIM + k]     = lo;
    row[2 * CDIM + k] = hi;
}

// ---------------------------------------------------------------------------
// Weight transpose + split: w [1024][Nw] -> out [Nw][3072] = [hi | hi | lo]
// ---------------------------------------------------------------------------
__global__ void __launch_bounds__(1024)
conv_wt_kernel(const float* __restrict__ w, __nv_bfloat16* __restrict__ out, int Nw)
{
    __shared__ float tile[32][33];
    const int n0 = blockIdx.x * 32;
    const int k0 = blockIdx.y * 32;
    tile[threadIdx.y][threadIdx.x] = w[(size_t)(k0 + threadIdx.y) * Nw + n0 + threadIdx.x];
    __syncthreads();
    const int n = n0 + threadIdx.y;
    const int k = k0 + threadIdx.x;
    const float a = tile[threadIdx.x][threadIdx.y];
    const __nv_bfloat16 hi = __float2bfloat16(a);
    const __nv_bfloat16 lo = __float2bfloat16(a - __bfloat162float(hi));
    __nv_bfloat16* row = out + (size_t)n * KEFF;
    row[k]            = hi;
    row[CDIM + k]     = hi;
    row[2 * CDIM + k] = lo;
}

// ---------------------------------------------------------------------------
// Attention prep: split Q/K per head  g_q/g_k[bh][seg][t][d]
// ---------------------------------------------------------------------------
__global__ void __launch_bounds__(256)
prep_qk_kernel()
{
    const int idx = blockIdx.x * 256 + threadIdx.x;   // over MROWS*CDIM
    const int row = idx >> 10;          // 0..4095
    const int c   = idx & 1023;
    const int t   = row & (SEQ - 1);
    const int b   = row >> 11;
    const int h   = c >> 6;
    const int d   = c & 63;
    const int bh  = b * NHEAD + h;

    const float qv = g_qkv[(size_t)row * C3 + c];
    const float kv = g_qkv[(size_t)row * C3 + CDIM + c];
    const __nv_bfloat16 qhi = __float2bfloat16(qv);
    const __nv_bfloat16 qlo = __float2bfloat16(qv - __bfloat162float(qhi));
    const __nv_bfloat16 khi = __float2bfloat16(kv);
    const __nv_bfloat16 klo = __float2bfloat16(kv - __bfloat162float(khi));
    const size_t base0 = ((size_t)(bh * 2 + 0) * SEQ + t) * HDIM + d;
    const size_t base1 = ((size_t)(bh * 2 + 1) * SEQ + t) * HDIM + d;
    g_q[base0] = qhi;  g_q[base1] = qlo;
    g_k[base0] = khi;  g_k[base1] = klo;
}

// ---------------------------------------------------------------------------
// Attention prep: transposed split V   g_vt[bh][seg][d][t]
// ---------------------------------------------------------------------------
__global__ void __launch_bounds__(1024)
prep_vt_kernel()
{
    __shared__ float tile[32][33];
    const int bh = blockIdx.z;
    const int b  = bh >> 4;
    const int h  = bh & 15;
    const int t0 = blockIdx.x * 32;
    const int d0 = blockIdx.y * 32;

    tile[threadIdx.y][threadIdx.x] =
        g_qkv[(size_t)(b * SEQ + t0 + threadIdx.y) * C3 + 2 * CDIM + h * HDIM + d0 + threadIdx.x];
    __syncthreads();
    const int d = d0 + threadIdx.y;
    const int t = t0 + threadIdx.x;
    const float v = tile[threadIdx.x][threadIdx.y];
    const __nv_bfloat16 hi = __float2bfloat16(v);
    const __nv_bfloat16 lo = __float2bfloat16(v - __bfloat162float(hi));
    g_vt[((size_t)(bh * 2 + 0) * HDIM + d) * SEQ + t] = hi;
    g_vt[((size_t)(bh * 2 + 1) * HDIM + d) * SEQ + t] = lo;
}

// ---------------------------------------------------------------------------
// Tensor-core bf16 GEMM (validated R5): out = A[M][KEFF] * Bt[N][KEFF] + bias
// ---------------------------------------------------------------------------
#define GEMM_DYN_SMEM (2 * 32768)

__global__ void __launch_bounds__(256, 2)
gemm_mma_kernel(const __nv_bfloat16* __restrict__ A, const __nv_bfloat16* __restrict__ Bt,
                const float* __restrict__ bias, float* __restrict__ out, int Nout)
{
    extern __shared__ __align__(1024) char dyn[];
    const uint32_t tiles = smem_u32(dyn);

    const int tid = threadIdx.x;
    const int wid = tid >> 5;
    const int lane = tid & 31;
    const int wm = wid & 1;
    const int wn = wid >> 1;
    const int m0 = blockIdx.y * 128;
    const int n0 = blockIdx.x * 128;

    const __nv_bfloat16* Arow = A  + (size_t)m0 * KEFF;
    const __nv_bfloat16* Brow = Bt + (size_t)n0 * KEFF;

    auto load_chunk = [&](int c, int buf) {
        const uint32_t abase = tiles + buf * 32768;
        const uint32_t bbase = abase + 16384;
        const __nv_bfloat16* ag = Arow + c * 64;
        const __nv_bfloat16* bg = Brow + c * 64;
#pragma unroll
        for (int i = 0; i < 4; ++i) {
            const int g   = tid + 256 * i;
            const int row = g >> 3;
            const int gc  = g & 7;
            const uint32_t off = SWZ((uint32_t)(row * 128 + gc * 16));
            cp_async16(abase + off, (const char*)(ag + (size_t)row * KEFF) + gc * 16);
            cp_async16(bbase + off, (const char*)(bg + (size_t)row * KEFF) + gc * 16);
        }
        CP_COMMIT();
    };

    float acc[4][4][4];
#pragma unroll
    for (int mi = 0; mi < 4; ++mi)
#pragma unroll
        for (int ni = 0; ni < 4; ++ni)
#pragma unroll
            for (int r = 0; r < 4; ++r) acc[mi][ni][r] = 0.f;

    const int l15 = lane & 15;
    const int lhi16 = (lane >> 4) * 16;
    const int b_row = ((lane & 16) >> 1) + (lane & 7);
    const int b_khalf = (lane & 8) ? 16 : 0;

    load_chunk(0, 0);

    for (int c = 0; c < NCHUNK; ++c) {
        const int b = c & 1;
        if (c + 1 < NCHUNK) {
            load_chunk(c + 1, 1 - b);
            CP_WAIT(1);
        } else {
            CP_WAIT(0);
        }
        __syncthreads();

        const uint32_t abase = tiles + b * 32768;
        const uint32_t bbase = abase + 16384;

#pragma unroll
        for (int ks = 0; ks < 4; ++ks) {
            const int kb = ks * 32;
            uint32_t afr[4][4];
#pragma unroll
            for (int mi = 0; mi < 4; ++mi) {
                const int row = wm * 64 + mi * 16 + l15;
                ldmx4(afr[mi], abase + SWZ((uint32_t)(row * 128 + kb + lhi16)));
            }
            uint32_t bfr[2][4];
#pragma unroll
            for (int nj = 0; nj < 2; ++nj) {
                const int row = wn * 32 + nj * 16 + b_row;
                ldmx4(bfr[nj], bbase + SWZ((uint32_t)(row * 128 + kb + b_khalf)));
            }
#pragma unroll
            for (int mi = 0; mi < 4; ++mi) {
#pragma unroll
                for (int ni = 0; ni < 4; ++ni)
                    mma16816(acc[mi][ni], afr[mi], &bfr[ni >> 1][(ni & 1) * 2]);
            }
        }
        __syncthreads();
    }

    const int tr = lane >> 2;
    const int tc = (lane & 3) * 2;
#pragma unroll
    for (int mi = 0; mi < 4; ++mi) {
#pragma unroll
        for (int ni = 0; ni < 4; ++ni) {
            const int gr = m0 + wm * 64 + mi * 16 + tr;
            const int gc = n0 + wn * 32 + ni * 8 + tc;
            const float b0 = bias[gc], b1 = bias[gc + 1];
            float2 v0 = make_float2(acc[mi][ni][0] + b0, acc[mi][ni][1] + b1);
            float2 v1 = make_float2(acc[mi][ni][2] + b0, acc[mi][ni][3] + b1);
            *(float2*)(out + (size_t)gr * Nout + gc)       = v0;
            *(float2*)(out + (size_t)(gr + 8) * Nout + gc) = v1;
        }
    }
}

// ---------------------------------------------------------------------------
// Tensor-core flash attention (causal, split-bf16 both matmuls).
// Block = (b,h, 64-query tile). 8 warps: wr = wid>>1 (16-row band),
// wc = wid&1 (32-col band). Per warp: 1x4 m16n8 tiles for S and O.
// Epilogue writes split-bf16 directly into g_abig ([hi|lo|hi]).
// smem tiles (each 8KB, 64 rows x 128B, SW128):
//   QHI 0, QLO 8K, PHI 16K, PLO 24K, stages at 32K/64K: {KHI,KLO,VTHI,VTLO}
// ---------------------------------------------------------------------------
#define ATT2_SMEM 98304

__global__ void __launch_bounds__(256)
attention_tc_kernel()
{
    extern __shared__ __align__(1024) char dyn[];
    __shared__ float sMax[2][64];
    __shared__ float sSum[2][64];

    const uint32_t sb = smem_u32(dyn);
    const int tid  = threadIdx.x;
    const int wid  = tid >> 5;
    const int lane = tid & 31;
    const int wr = wid >> 1;             // 0..3
    const int wc = wid & 1;              // 0..1

    const int qi = gridDim.x - 1 - blockIdx.x;   // heavy tiles first
    const int bh = blockIdx.y;
    const int b  = bh >> 4;
    const int h  = bh & 15;

    const int l15 = lane & 15;
    const int lhi16 = (lane >> 4) * 16;
    const int b_row = ((lane & 16) >> 1) + (lane & 7);
    const int b_khalf = (lane & 8) ? 16 : 0;
    const int tr = lane >> 2;
    const int tc2 = (lane & 3) * 2;

    // ---- Q tiles (hi/lo), cp.async group 0 ----
    {
#pragma unroll
        for (int i = 0; i < 4; ++i) {
            const int g = tid + 256 * i;            // 0..1023
            const int seg = g >> 9;
            const int r   = (g >> 3) & 63;
            const int gc  = g & 7;
            const uint32_t dst = sb + seg * 8192 + SWZ((uint32_t)(r * 128 + gc * 16));
            const char* src = (const char*)&g_q[((size_t)(bh * 2 + seg) * SEQ + qi * 64 + r) * HDIM] + gc * 16;
            cp_async16(dst, src);
        }
        CP_COMMIT();
    }

    // K/V stage loader
    auto load_kv = [&](int kt, int buf) {
        const uint32_t stage = sb + 32768 + buf * 32768;
#pragma unroll
        for (int i = 0; i < 4; ++i) {      // K hi/lo
            const int g = tid + 256 * i;
            const int seg = g >> 9;
            const int r   = (g >> 3) & 63;
            const int gc  = g & 7;
            const uint32_t dst = stage + seg * 8192 + SWZ((uint32_t)(r * 128 + gc * 16));
            const char* src = (const char*)&g_k[((size_t)(bh * 2 + seg) * SEQ + kt * 64 + r) * HDIM] + gc * 16;
            cp_async16(dst, src);
        }
#pragma unroll
        for (int i = 0; i < 4; ++i) {      // Vt hi/lo
            const int g = tid + 256 * i;
            const int seg = g >> 9;
            const int d   = (g >> 3) & 63;
            const int gc  = g & 7;
            const uint32_t dst = stage + 16384 + seg * 8192 + SWZ((uint32_t)(d * 128 + gc * 16));
            const char* src = (const char*)&g_vt[((size_t)(bh * 2 + seg) * HDIM + d) * SEQ + kt * 64] + gc * 16;
            cp_async16(dst, src);
        }
        CP_COMMIT();
    };

    load_kv(0, 0);

    float o[4][4];
#pragma unroll
    for (int ni = 0; ni < 4; ++ni)
#pragma unroll
        for (int r = 0; r < 4; ++r) o[ni][r] = 0.f;
    float m_st[2] = {-INFINITY, -INFINITY};
    float l_st[2] = {0.f, 0.f};

    const int rowL0 = 16 * wr + tr;         // local rows this thread owns
    const int rowL1 = rowL0 + 8;

    for (int kt = 0; kt <= qi; ++kt) {
        const int buf = kt & 1;
        if (kt < qi) { load_kv(kt + 1, 1 - buf); CP_WAIT(1); }
        else         { CP_WAIT(0); }
        __syncthreads();

        const uint32_t stage = sb + 32768 + buf * 32768;

        // ---- S = Q K^T (3-term split, k=64 per seg) ----
        float sacc[4][4];
#pragma unroll
        for (int ni = 0; ni < 4; ++ni)
#pragma unroll
            for (int r = 0; r < 4; ++r) sacc[ni][r] = 0.f;

#pragma unroll
        for (int kb = 0; kb < 4; ++kb) {
            const int kbb = kb * 32;
            uint32_t aHi[4], aLo[4];
            ldmx4(aHi, sb +        SWZ((uint32_t)((16 * wr + l15) * 128 + kbb + lhi16)));
            ldmx4(aLo, sb + 8192 + SWZ((uint32_t)((16 * wr + l15) * 128 + kbb + lhi16)));
            uint32_t bHi[2][4], bLo[2][4];
#pragma unroll
            for (int nj = 0; nj < 2; ++nj) {
                const uint32_t ro = (uint32_t)((32 * wc + nj * 16 + b_row) * 128 + kbb + b_khalf);
                ldmx4(bHi[nj], stage +        SWZ(ro));
                ldmx4(bLo[nj], stage + 8192 + SWZ(ro));
            }
#pragma unroll
            for (int ni = 0; ni < 4; ++ni) {
                mma16816(sacc[ni], aHi, &bHi[ni >> 1][(ni & 1) * 2]);
                mma16816(sacc[ni], aLo, &bHi[ni >> 1][(ni & 1) * 2]);
                mma16816(sacc[ni], aHi, &bLo[ni >> 1][(ni & 1) * 2]);
            }
        }

        // ---- scale + causal mask ----
        if (kt == qi) {
#pragma unroll
            for (int ni = 0; ni < 4; ++ni) {
#pragma unroll
                for (int r = 0; r < 4; ++r) {
                    const int row = (r < 2) ? rowL0 : rowL1;
                    const int col = 32 * wc + ni * 8 + tc2 + (r & 1);
                    sacc[ni][r] = (col > row) ? -INFINITY : sacc[ni][r] * 0.125f;
                }
            }
        } else {
#pragma unroll
            for (int ni = 0; ni < 4; ++ni)
#pragma unroll
                for (int r = 0; r < 4; ++r) sacc[ni][r] *= 0.125f;
        }

        // ---- row max (warp 32-col max -> smem -> combine) ----
        float mx0 = -INFINITY, mx1 = -INFINITY;
#pragma unroll
        for (int ni = 0; ni < 4; ++ni) {
            mx0 = fmaxf(mx0, fmaxf(sacc[ni][0], sacc[ni][1]));
            mx1 = fmaxf(mx1, fmaxf(sacc[ni][2], sacc[ni][3]));
        }
        mx0 = fmaxf(mx0, __shfl_xor_sync(0xffffffffu, mx0, 1));
        mx0 = fmaxf(mx0, __shfl_xor_sync(0xffffffffu, mx0, 2));
        mx1 = fmaxf(mx1, __shfl_xor_sync(0xffffffffu, mx1, 1));
        mx1 = fmaxf(mx1, __shfl_xor_sync(0xffffffffu, mx1, 2));
        if ((lane & 3) == 0) {
            sMax[wc][rowL0] = mx0;
            sMax[wc][rowL1] = mx1;
        }
        __syncthreads();

        const float mt0 = fmaxf(sMax[0][rowL0], sMax[1][rowL0]);
        const float mt1 = fmaxf(sMax[0][rowL1], sMax[1][rowL1]);
        const float mn0 = fmaxf(m_st[0], mt0);
        const float mn1 = fmaxf(m_st[1], mt1);
        const float corr0 = __expf(m_st[0] - mn0);
        const float corr1 = __expf(m_st[1] - mn1);
        m_st[0] = mn0;  m_st[1] = mn1;

        // ---- exp, partial row sums, store split P, rescale O ----
        float rs0 = 0.f, rs1 = 0.f;
#pragma unroll
        for (int ni = 0; ni < 4; ++ni) {
            const int colB = (32 * wc + ni * 8 + tc2) * 2;   // byte col offset
            // row pair 0 (regs 0,1)
            {
                const float p0 = __expf(sacc[ni][0] - mn0);
                const float p1 = __expf(sacc[ni][1] - mn0);
                rs0 += p0 + p1;
                const __nv_bfloat16 h0 = __float2bfloat16(p0);
                const __nv_bfloat16 h1 = __float2bfloat16(p1);
                const __nv_bfloat16 l0 = __float2bfloat16(p0 - __bfloat162float(h0));
                const __nv_bfloat16 l1 = __float2bfloat16(p1 - __bfloat162float(h1));
                const uint32_t off = SWZ((uint32_t)(rowL0 * 128 + colB));
                *(__nv_bfloat162*)(dyn + 16384 + off) = __nv_bfloat162(h0, h1);
                *(__nv_bfloat162*)(dyn + 24576 + off) = __nv_bfloat162(l0, l1);
            }
            // row pair 1 (regs 2,3)
            {
                const float p0 = __expf(sacc[ni][2] - mn1);
                const float p1 = __expf(sacc[ni][3] - mn1);
                rs1 += p0 + p1;
                const __nv_bfloat16 h0 = __float2bfloat16(p0);
                const __nv_bfloat16 h1 = __float2bfloat16(p1);
                const __nv_bfloat16 l0 = __float2bfloat16(p0 - __bfloat162float(h0));
                const __nv_bfloat16 l1 = __float2bfloat16(p1 - __bfloat162float(h1));
                const uint32_t off = SWZ((uint32_t)(rowL1 * 128 + colB));
                *(__nv_bfloat162*)(dyn + 16384 + off) = __nv_bfloat162(h0, h1);
                *(__nv_bfloat162*)(dyn + 24576 + off) = __nv_bfloat162(l0, l1);
            }
            o[ni][0] *= corr0; o[ni][1] *= corr0;
            o[ni][2] *= corr1; o[ni][3] *= corr1;
        }
        rs0 += __shfl_xor_sync(0xffffffffu, rs0, 1);
        rs0 += __shfl_xor_sync(0xffffffffu, rs0, 2);
        rs1 += __shfl_xor_sync(0xffffffffu, rs1, 1);
        rs1 += __shfl_xor_sync(0xffffffffu, rs1, 2);
        if ((lane & 3) == 0) {
            sSum[wc][rowL0] = rs0;
            sSum[wc][rowL1] = rs1;
        }
        __syncthreads();

        l_st[0] = l_st[0] * corr0 + sSum[0][rowL0] + sSum[1][rowL0];
        l_st[1] = l_st[1] * corr1 + sSum[0][rowL1] + sSum[1][rowL1];

        // ---- O += P V (3-term split) ----
#pragma unroll
        for (int kb = 0; kb < 4; ++kb) {
            const int kbb = kb * 32;
            uint32_t aHi[4], aLo[4];
            ldmx4(aHi, sb + 16384 + SWZ((uint32_t)((16 * wr + l15) * 128 + kbb + lhi16)));
            ldmx4(aLo, sb + 24576 + SWZ((uint32_t)((16 * wr + l15) * 128 + kbb + lhi16)));
            uint32_t bHi[2][4], bLo[2][4];
#pragma unroll
            for (int nj = 0; nj < 2; ++nj) {
                const uint32_t ro = (uint32_t)((32 * wc + nj * 16 + b_row) * 128 + kbb + b_khalf);
                ldmx4(bHi[nj], stage + 16384 +        SWZ(ro));
                ldmx4(bLo[nj], stage + 16384 + 8192 + SWZ(ro));
            }
#pragma unroll
            for (int ni = 0; ni < 4; ++ni) {
                mma16816(o[ni], aHi, &bHi[ni >> 1][(ni & 1) * 2]);
                mma16816(o[ni], aLo, &bHi[ni >> 1][(ni & 1) * 2]);
                mma16816(o[ni], aHi, &bLo[ni >> 1][(ni & 1) * 2]);
            }
        }
        __syncthreads();   // done reading stage buf + P before next iter overwrites
    }

    // ---- normalize + write split-bf16 proj input directly ----
    const float inv0 = 1.f / l_st[0];
    const float inv1 = 1.f / l_st[1];
    const int q0 = qi * 64 + rowL0;
    const int q1 = qi * 64 + rowL1;
    __nv_bfloat16* r0p = g_abig + (size_t)(b * SEQ + q0) * KEFF;
    __nv_bfloat16* r1p = g_abig + (size_t)(b * SEQ + q1) * KEFF;
#pragma unroll
    for (int ni = 0; ni < 4; ++ni) {
        const int c = h * HDIM + 32 * wc + ni * 8 + tc2;
        {
            const float p0 = o[ni][0] * inv0;
            const float p1 = o[ni][1] * inv0;
            const __nv_bfloat16 h0 = __float2bfloat16(p0);
            const __nv_bfloat16 h1 = __float2bfloat16(p1);
            const __nv_bfloat16 l0 = __float2bfloat16(p0 - __bfloat162float(h0));
            const __nv_bfloat16 l1 = __float2bfloat16(p1 - __bfloat162float(h1));
            *(__nv_bfloat162*)(r0p + c)            = __nv_bfloat162(h0, h1);
            *(__nv_bfloat162*)(r0p + CDIM + c)     = __nv_bfloat162(l0, l1);
            *(__nv_bfloat162*)(r0p + 2 * CDIM + c) = __nv_bfloat162(h0, h1);
        }
        {
            const float p0 = o[ni][2] * inv1;
            const float p1 = o[ni][3] * inv1;
            const __nv_bfloat16 h0 = __float2bfloat16(p0);
            const __nv_bfloat16 h1 = __float2bfloat16(p1);
            const __nv_bfloat16 l0 = __float2bfloat16(p0 - __bfloat162float(h0));
            const __nv_bfloat16 l1 = __float2bfloat16(p1 - __bfloat162float(h1));
            *(__nv_bfloat162*)(r1p + c)            = __nv_bfloat162(h0, h1);
            *(__nv_bfloat162*)(r1p + CDIM + c)     = __nv_bfloat162(l0, l1);
            *(__nv_bfloat162*)(r1p + 2 * CDIM + c) = __nv_bfloat162(h0, h1);
        }
    }
}

// ---------------------------------------------------------------------------
// launch
// ---------------------------------------------------------------------------
extern "C" void kernel_launch(void* const* d_in, const int* in_sizes, int n_in,
                              void* d_out, int out_size)
{
    const float* x      = (const float*)d_in[0];
    const float* w_qkv  = (const float*)d_in[1];
    const float* b_qkv  = (const float*)d_in[2];
    const float* w_proj = (const float*)d_in[3];
    const float* b_proj = (const float*)d_in[4];
    float* out = (float*)d_out;

    float* qkv = nullptr;
    __nv_bfloat16* abig = nullptr; __nv_bfloat16* wqkvt = nullptr; __nv_bfloat16* wprojt = nullptr;
    cudaGetSymbolAddress((void**)&qkv,    g_qkv);
    cudaGetSymbolAddress((void**)&abig,   g_abig);
    cudaGetSymbolAddress((void**)&wqkvt,  g_wqkvt);
    cudaGetSymbolAddress((void**)&wprojt, g_wprojt);

    cudaFuncSetAttribute(gemm_mma_kernel,
                         cudaFuncAttributeMaxDynamicSharedMemorySize, GEMM_DYN_SMEM);
    cudaFuncSetAttribute(attention_tc_kernel,
                         cudaFuncAttributeMaxDynamicSharedMemorySize, ATT2_SMEM);

    // weight prep
    conv_wt_kernel<<<dim3(C3 / 32, CDIM / 32), dim3(32, 32)>>>(w_qkv, wqkvt, C3);
    conv_wt_kernel<<<dim3(CDIM / 32, CDIM / 32), dim3(32, 32)>>>(w_proj, wprojt, CDIM);

    // 1) qkv = x @ w_qkv + b_qkv
    conv_split_kernel<<<(MROWS * CDIM) / 256, 256>>>(x, abig);
    gemm_mma_kernel<<<dim3(C3 / 128, MROWS / 128), 256, GEMM_DYN_SMEM>>>(
        abig, wqkvt, b_qkv, qkv, C3);

    // 2) attention prep (split per-head Q/K, transposed split V)
    prep_qk_kernel<<<(MROWS * CDIM) / 256, 256>>>();
    prep_vt_kernel<<<dim3(SEQ / 32, HDIM / 32, NBH), dim3(32, 32)>>>();

    // 3) tensor-core flash attention -> writes split-bf16 into g_abig
    attention_tc_kernel<<<dim3(SEQ / 64, NBH), 256, ATT2_SMEM>>>();

    // 4) out = att @ w_proj + b_proj
    gemm_mma_kernel<<<dim3(CDIM / 128, MROWS / 128), 256, GEMM_DYN_SMEM>>>(
        abig, wprojt, b_proj, out, CDIM);
}